// round 3
// baseline (speedup 1.0000x reference)
#include <cuda_runtime.h>
#include <math.h>

typedef unsigned long long ULL;

// ---------------- constants ----------------
#define B_   64
#define TT   63          // time steps actually computed (T-1)
#define EE   512
#define HH   1024
#define VV   32000
#define G4   4096        // 4*H

// ---------------- scratch (device globals; no allocation) ----------------
__device__ float g_Wih0p[G4 * EE];          //  8.4 MB  gate-interleaved W_ih0
__device__ float g_Whh0p[G4 * HH];          // 16.8 MB  gate-interleaved W_hh0
__device__ float g_W1cat[G4 * 2 * HH];      // 33.6 MB  [W_ih1 | W_hh1] interleaved
__device__ float g_b0p[G4];
__device__ float g_b1p[G4];
__device__ float g_G0x[TT * B_ * G4];       // 66 MB    x-side layer0 gates (+bias)
__device__ float g_H1 [TT * B_ * HH];       // 16.5 MB  h1 per step
__device__ float g_h0buf[2][B_ * HH];
__device__ float g_h1buf[2][B_ * HH];
__device__ float g_c0s[B_ * HH];
__device__ float g_c1s[B_ * HH];
__device__ ULL   g_keys[TT * B_];           // packed argmax keys, indexed t*64+b

// ---------------- helpers ----------------
static __device__ __forceinline__ ULL dup2(float b) {
    ULL r; unsigned u = __float_as_uint(b);
    asm("mov.b64 %0, {%1, %1};" : "=l"(r) : "r"(u));
    return r;
}
static __device__ __forceinline__ void fma2(ULL& acc, ULL a, ULL b) {
    asm("fma.rn.f32x2 %0, %1, %2, %0;" : "+l"(acc) : "l"(a), "l"(b));
}
static __device__ __forceinline__ ULL mk2(float x, float y) {
    ULL r;
    asm("mov.b64 %0, {%1, %2};" : "=l"(r)
        : "r"(__float_as_uint(x)), "r"(__float_as_uint(y)));
    return r;
}
static __device__ __forceinline__ float selh(ULL u, int hi) {
    return __uint_as_float(hi ? (unsigned)(u >> 32) : (unsigned)u);
}
static __device__ __forceinline__ float sigf(float x) { return 1.0f / (1.0f + expf(-x)); }
static __device__ __forceinline__ unsigned fordu(float v) {
    unsigned u = __float_as_uint(v);
    return u ^ (((int)u >> 31) | 0x80000000u);
}
static __device__ __forceinline__ ULL mkkey(float v, int col) {
    return ((ULL)fordu(v) << 32) | (ULL)(0xFFFFFFFFu - (unsigned)col);
}

// ---------------- 1) pack / init ----------------
__global__ void pack_kernel(const float* __restrict__ Wih0, const float* __restrict__ Whh0,
                            const float* __restrict__ Wih1, const float* __restrict__ Whh1,
                            const float* __restrict__ bih0, const float* __restrict__ bhh0,
                            const float* __restrict__ bih1, const float* __restrict__ bhh1) {
    int i = blockIdx.x * 256 + threadIdx.x;           // covers 4096*2048
    if (i < TT * B_) g_keys[i] = 0ull;
    int rp  = i >> 11;                                // new (interleaved) row
    int k   = i & 2047;
    int old = ((rp & 3) << 10) + (rp >> 2);           // gate*1024 + hidden
    g_W1cat[i] = (k < HH) ? Wih1[old * HH + k] : Whh1[old * HH + (k - HH)];
    if (k < EE) g_Wih0p[rp * EE + k] = Wih0[old * EE + k];
    if (k < HH) g_Whh0p[rp * HH + k] = Whh0[old * HH + k];
    if (k == 0) {
        g_b0p[rp] = bih0[old] + bhh0[old];
        g_b1p[rp] = bih1[old] + bhh1[old];
    }
}

// ---------------- 2) h0 = initial_state @ enc_proj_W^T  (also c0,h1,c1) ----------------
// tile 64x32, 128 threads, grid 32, K=2048
__global__ __launch_bounds__(128) void h0init_kernel(const float* __restrict__ S,
                                                     const float* __restrict__ EW) {
    __shared__ float A_sm[32 * 66];
    __shared__ float B_sm[32 * 36];
    int tid = threadIdx.x, tr = tid >> 3, tc = tid & 7;
    int cb = blockIdx.x * 32;
    ULL acc[2][4] = {{0,0,0,0},{0,0,0,0}};
    float pA[16], pB[8];
    #pragma unroll
    for (int e = 0; e < 16; e++) { int idx = e*128+tid; pA[e] = S[(idx>>5)*2048 + (idx&31)]; }
    #pragma unroll
    for (int e = 0; e < 8;  e++) { int idx = e*128+tid; pB[e] = EW[(size_t)(cb+(idx>>5))*2048 + (idx&31)]; }
    for (int k0 = 0; k0 < 2048; k0 += 32) {
        __syncthreads();
        #pragma unroll
        for (int e = 0; e < 16; e++) { int idx = e*128+tid; A_sm[(idx&31)*66 + (idx>>5)] = pA[e]; }
        #pragma unroll
        for (int e = 0; e < 8;  e++) { int idx = e*128+tid; B_sm[(idx&31)*36 + (idx>>5)] = pB[e]; }
        __syncthreads();
        int kn = k0 + 32;
        if (kn < 2048) {
            #pragma unroll
            for (int e = 0; e < 16; e++) { int idx = e*128+tid; pA[e] = S[(idx>>5)*2048 + kn + (idx&31)]; }
            #pragma unroll
            for (int e = 0; e < 8;  e++) { int idx = e*128+tid; pB[e] = EW[(size_t)(cb+(idx>>5))*2048 + kn + (idx&31)]; }
        }
        #pragma unroll 8
        for (int kk = 0; kk < 32; kk++) {
            const ULL* ar = reinterpret_cast<const ULL*>(A_sm + kk * 66);
            ULL a0 = ar[2*tr], a1 = ar[2*tr+1];
            float4 bv = *reinterpret_cast<const float4*>(B_sm + kk*36 + 4*tc);
            ULL b0 = dup2(bv.x), b1 = dup2(bv.y), b2 = dup2(bv.z), b3 = dup2(bv.w);
            fma2(acc[0][0], a0, b0); fma2(acc[1][0], a1, b0);
            fma2(acc[0][1], a0, b1); fma2(acc[1][1], a1, b1);
            fma2(acc[0][2], a0, b2); fma2(acc[1][2], a1, b2);
            fma2(acc[0][3], a0, b3); fma2(acc[1][3], a1, b3);
        }
    }
    #pragma unroll
    for (int p = 0; p < 2; p++) {
        #pragma unroll
        for (int hi = 0; hi < 2; hi++) {
            int r = 4*tr + 2*p + hi;
            #pragma unroll
            for (int c = 0; c < 4; c++) {
                int col = cb + 4*tc + c;
                float v = selh(acc[p][c], hi);
                g_h0buf[0][r*HH + col] = v;
                g_c0s   [r*HH + col]   = v;
                g_h1buf[0][r*HH + col] = v;
                g_c1s   [r*HH + col]   = v;
            }
        }
    }
}

// ---------------- 3) G0x = emb[ids] @ Wih0p^T + b0p  ----------------
// tile 64x128, 256 threads, grid (63, 32), K=512
__global__ __launch_bounds__(256) void embx_kernel(const int* __restrict__ ids,
                                                   const float* __restrict__ emb) {
    __shared__ float A_sm[32 * 66];
    __shared__ float B_sm[32 * 132];
    __shared__ int   ids_sm[B_];
    int tid = threadIdx.x, tr = tid >> 5, tc = tid & 31;
    int t = blockIdx.x, cb = blockIdx.y * 128;
    if (tid < B_) ids_sm[tid] = ids[tid * 64 + t];
    __syncthreads();
    ULL acc[4][4] = {{0,0,0,0},{0,0,0,0},{0,0,0,0},{0,0,0,0}};
    float pA[8], pB[16];
    #pragma unroll
    for (int e = 0; e < 8;  e++) { int idx = e*256+tid; pA[e] = emb[(size_t)ids_sm[idx>>5]*EE + (idx&31)]; }
    #pragma unroll
    for (int e = 0; e < 16; e++) { int idx = e*256+tid; pB[e] = g_Wih0p[(size_t)(cb+(idx>>5))*EE + (idx&31)]; }
    for (int k0 = 0; k0 < EE; k0 += 32) {
        __syncthreads();
        #pragma unroll
        for (int e = 0; e < 8;  e++) { int idx = e*256+tid; A_sm[(idx&31)*66  + (idx>>5)] = pA[e]; }
        #pragma unroll
        for (int e = 0; e < 16; e++) { int idx = e*256+tid; B_sm[(idx&31)*132 + (idx>>5)] = pB[e]; }
        __syncthreads();
        int kn = k0 + 32;
        if (kn < EE) {
            #pragma unroll
            for (int e = 0; e < 8;  e++) { int idx = e*256+tid; pA[e] = emb[(size_t)ids_sm[idx>>5]*EE + kn + (idx&31)]; }
            #pragma unroll
            for (int e = 0; e < 16; e++) { int idx = e*256+tid; pB[e] = g_Wih0p[(size_t)(cb+(idx>>5))*EE + kn + (idx&31)]; }
        }
        #pragma unroll 4
        for (int kk = 0; kk < 32; kk++) {
            const ULL* ar = reinterpret_cast<const ULL*>(A_sm + kk * 66);
            ULL a0 = ar[4*tr], a1 = ar[4*tr+1], a2 = ar[4*tr+2], a3 = ar[4*tr+3];
            float4 bv = *reinterpret_cast<const float4*>(B_sm + kk*132 + 4*tc);
            ULL b0 = dup2(bv.x), b1 = dup2(bv.y), b2 = dup2(bv.z), b3 = dup2(bv.w);
            fma2(acc[0][0], a0, b0); fma2(acc[1][0], a1, b0); fma2(acc[2][0], a2, b0); fma2(acc[3][0], a3, b0);
            fma2(acc[0][1], a0, b1); fma2(acc[1][1], a1, b1); fma2(acc[2][1], a2, b1); fma2(acc[3][1], a3, b1);
            fma2(acc[0][2], a0, b2); fma2(acc[1][2], a1, b2); fma2(acc[2][2], a2, b2); fma2(acc[3][2], a3, b2);
            fma2(acc[0][3], a0, b3); fma2(acc[1][3], a1, b3); fma2(acc[2][3], a2, b3); fma2(acc[3][3], a3, b3);
        }
    }
    float* outp = g_G0x + (size_t)(t * B_) * G4;
    float4 bb = *reinterpret_cast<const float4*>(g_b0p + cb + 4*tc);
    #pragma unroll
    for (int r8 = 0; r8 < 8; r8++) {
        int r = 8*tr + r8, p = r8 >> 1, hi = r8 & 1;
        float4 v;
        v.x = selh(acc[p][0], hi) + bb.x;
        v.y = selh(acc[p][1], hi) + bb.y;
        v.z = selh(acc[p][2], hi) + bb.z;
        v.w = selh(acc[p][3], hi) + bb.w;
        *reinterpret_cast<float4*>(outp + (size_t)r*G4 + cb + 4*tc) = v;
    }
}

// ---------------- 4) fused LSTM cell step (one layer) ----------------
// tile 64x32 (gate cols), 128 threads, grid 128
__global__ __launch_bounds__(128) void cell_kernel(int t, int layer) {
    __shared__ float A_sm[32 * 66];
    __shared__ float B_sm[32 * 36];
    int tid = threadIdx.x, tr = tid >> 3, tc = tid & 7;
    int cb = blockIdx.x * 32;
    int in = t & 1, out = in ^ 1;

    const float *A1, *A2, *W;
    const float* initp = nullptr;
    float *cst, *hout, *hcopy;
    int K;
    if (layer == 0) {
        A1 = g_h0buf[in]; A2 = g_h0buf[in]; W = g_Whh0p; K = HH;
        initp = g_G0x + (size_t)(t * B_) * G4;
        cst = g_c0s; hout = g_h0buf[out]; hcopy = nullptr;
    } else {
        A1 = g_h0buf[out]; A2 = g_h1buf[in]; W = g_W1cat; K = 2 * HH;
        cst = g_c1s; hout = g_h1buf[out];
        hcopy = g_H1 + (size_t)(t * B_) * HH;
    }

    int gc0 = cb + 4 * tc;
    ULL acc[2][4];
    if (layer == 0) {
        #pragma unroll
        for (int p = 0; p < 2; p++) {
            int r0 = 4*tr + 2*p;
            float4 i0 = *reinterpret_cast<const float4*>(initp + (size_t)r0     * G4 + gc0);
            float4 i1 = *reinterpret_cast<const float4*>(initp + (size_t)(r0+1) * G4 + gc0);
            acc[p][0] = mk2(i0.x, i1.x); acc[p][1] = mk2(i0.y, i1.y);
            acc[p][2] = mk2(i0.z, i1.z); acc[p][3] = mk2(i0.w, i1.w);
        }
    } else {
        float4 bb = *reinterpret_cast<const float4*>(g_b1p + gc0);
        acc[0][0] = dup2(bb.x); acc[1][0] = dup2(bb.x);
        acc[0][1] = dup2(bb.y); acc[1][1] = dup2(bb.y);
        acc[0][2] = dup2(bb.z); acc[1][2] = dup2(bb.z);
        acc[0][3] = dup2(bb.w); acc[1][3] = dup2(bb.w);
    }

    float pA[16], pB[8];
    #pragma unroll
    for (int e = 0; e < 16; e++) { int idx = e*128+tid; pA[e] = A1[(idx>>5)*HH + (idx&31)]; }
    #pragma unroll
    for (int e = 0; e < 8;  e++) { int idx = e*128+tid; pB[e] = W[(size_t)(cb+(idx>>5))*K + (idx&31)]; }
    for (int k0 = 0; k0 < K; k0 += 32) {
        __syncthreads();
        #pragma unroll
        for (int e = 0; e < 16; e++) { int idx = e*128+tid; A_sm[(idx&31)*66 + (idx>>5)] = pA[e]; }
        #pragma unroll
        for (int e = 0; e < 8;  e++) { int idx = e*128+tid; B_sm[(idx&31)*36 + (idx>>5)] = pB[e]; }
        __syncthreads();
        int kn = k0 + 32;
        if (kn < K) {
            const float* Asrc = (kn < HH) ? (A1 + kn) : (A2 + (kn - HH));
            #pragma unroll
            for (int e = 0; e < 16; e++) { int idx = e*128+tid; pA[e] = Asrc[(idx>>5)*HH + (idx&31)]; }
            #pragma unroll
            for (int e = 0; e < 8;  e++) { int idx = e*128+tid; pB[e] = W[(size_t)(cb+(idx>>5))*K + kn + (idx&31)]; }
        }
        #pragma unroll 8
        for (int kk = 0; kk < 32; kk++) {
            const ULL* ar = reinterpret_cast<const ULL*>(A_sm + kk * 66);
            ULL a0 = ar[2*tr], a1 = ar[2*tr+1];
            float4 bv = *reinterpret_cast<const float4*>(B_sm + kk*36 + 4*tc);
            ULL b0 = dup2(bv.x), b1 = dup2(bv.y), b2 = dup2(bv.z), b3 = dup2(bv.w);
            fma2(acc[0][0], a0, b0); fma2(acc[1][0], a1, b0);
            fma2(acc[0][1], a0, b1); fma2(acc[1][1], a1, b1);
            fma2(acc[0][2], a0, b2); fma2(acc[1][2], a1, b2);
            fma2(acc[0][3], a0, b3); fma2(acc[1][3], a1, b3);
        }
    }

    int j = (cb >> 2) + tc;                      // hidden unit index
    #pragma unroll
    for (int p = 0; p < 2; p++) {
        #pragma unroll
        for (int hi = 0; hi < 2; hi++) {
            int r = 4*tr + 2*p + hi;
            float iv = selh(acc[p][0], hi);
            float fv = selh(acc[p][1], hi);
            float gv = selh(acc[p][2], hi);
            float ov = selh(acc[p][3], hi);
            float cold = cst[r*HH + j];
            float cn = sigf(fv) * cold + sigf(iv) * tanhf(gv);
            float h  = sigf(ov) * tanhf(cn);
            cst[r*HH + j]  = cn;
            hout[r*HH + j] = h;
            if (hcopy) hcopy[r*HH + j] = h;
        }
    }
}

// ---------------- 5) logits = H1 @ proj_W^T + b, fused argmax ----------------
// tile 64x128, 256 threads, grid (63, 250), K=1024
__global__ __launch_bounds__(256) void proj_kernel(const float* __restrict__ PW,
                                                   const float* __restrict__ PB,
                                                   float* __restrict__ out) {
    __shared__ float A_sm[32 * 66];
    __shared__ float B_sm[32 * 132];
    int tid = threadIdx.x, tr = tid >> 5, tc = tid & 31;
    int t = blockIdx.x, cb = blockIdx.y * 128;
    const float* A = g_H1 + (size_t)(t * B_) * HH;
    ULL acc[4][4] = {{0,0,0,0},{0,0,0,0},{0,0,0,0},{0,0,0,0}};
    float pA[8], pB[16];
    #pragma unroll
    for (int e = 0; e < 8;  e++) { int idx = e*256+tid; pA[e] = A[(idx>>5)*HH + (idx&31)]; }
    #pragma unroll
    for (int e = 0; e < 16; e++) { int idx = e*256+tid; pB[e] = PW[(size_t)(cb+(idx>>5))*HH + (idx&31)]; }
    for (int k0 = 0; k0 < HH; k0 += 32) {
        __syncthreads();
        #pragma unroll
        for (int e = 0; e < 8;  e++) { int idx = e*256+tid; A_sm[(idx&31)*66  + (idx>>5)] = pA[e]; }
        #pragma unroll
        for (int e = 0; e < 16; e++) { int idx = e*256+tid; B_sm[(idx&31)*132 + (idx>>5)] = pB[e]; }
        __syncthreads();
        int kn = k0 + 32;
        if (kn < HH) {
            #pragma unroll
            for (int e = 0; e < 8;  e++) { int idx = e*256+tid; pA[e] = A[(idx>>5)*HH + kn + (idx&31)]; }
            #pragma unroll
            for (int e = 0; e < 16; e++) { int idx = e*256+tid; pB[e] = PW[(size_t)(cb+(idx>>5))*HH + kn + (idx&31)]; }
        }
        #pragma unroll 4
        for (int kk = 0; kk < 32; kk++) {
            const ULL* ar = reinterpret_cast<const ULL*>(A_sm + kk * 66);
            ULL a0 = ar[4*tr], a1 = ar[4*tr+1], a2 = ar[4*tr+2], a3 = ar[4*tr+3];
            float4 bv = *reinterpret_cast<const float4*>(B_sm + kk*132 + 4*tc);
            ULL b0 = dup2(bv.x), b1 = dup2(bv.y), b2 = dup2(bv.z), b3 = dup2(bv.w);
            fma2(acc[0][0], a0, b0); fma2(acc[1][0], a1, b0); fma2(acc[2][0], a2, b0); fma2(acc[3][0], a3, b0);
            fma2(acc[0][1], a0, b1); fma2(acc[1][1], a1, b1); fma2(acc[2][1], a2, b1); fma2(acc[3][1], a3, b1);
            fma2(acc[0][2], a0, b2); fma2(acc[1][2], a1, b2); fma2(acc[2][2], a2, b2); fma2(acc[3][2], a3, b2);
            fma2(acc[0][3], a0, b3); fma2(acc[1][3], a1, b3); fma2(acc[2][3], a2, b3); fma2(acc[3][3], a3, b3);
        }
    }
    float4 pb = *reinterpret_cast<const float4*>(PB + cb + 4*tc);
    float* lout = out + TT * B_;                 // logits after preds
    int gcb = cb + 4*tc;
    #pragma unroll
    for (int r8 = 0; r8 < 8; r8++) {
        int b = 8*tr + r8, p = r8 >> 1, hi = r8 & 1;
        float4 v;
        v.x = selh(acc[p][0], hi) + pb.x;
        v.y = selh(acc[p][1], hi) + pb.y;
        v.z = selh(acc[p][2], hi) + pb.z;
        v.w = selh(acc[p][3], hi) + pb.w;
        *reinterpret_cast<float4*>(lout + ((size_t)b * TT + t) * VV + gcb) = v;
        ULL key = mkkey(v.x, gcb);
        ULL k2  = mkkey(v.y, gcb + 1); if (k2 > key) key = k2;
        k2      = mkkey(v.z, gcb + 2); if (k2 > key) key = k2;
        k2      = mkkey(v.w, gcb + 3); if (k2 > key) key = k2;
        #pragma unroll
        for (int off = 16; off > 0; off >>= 1) {
            ULL o = __shfl_xor_sync(0xFFFFFFFFu, key, off);
            if (o > key) key = o;
        }
        if (tc == 0) atomicMax(&g_keys[t * B_ + b], key);
    }
}

// ---------------- 6) finalize preds ----------------
__global__ void preds_kernel(float* __restrict__ out) {
    int i = blockIdx.x * 256 + threadIdx.x;
    if (i >= TT * B_) return;
    ULL k = g_keys[i];
    unsigned col = 0xFFFFFFFFu - (unsigned)(k & 0xFFFFFFFFull);
    int t = i >> 6, b = i & 63;
    out[b * TT + t] = (float)col;
}

// ---------------- launch ----------------
extern "C" void kernel_launch(void* const* d_in, const int* in_sizes, int n_in,
                              void* d_out, int out_size) {
    const int*   ids    = (const int*)  d_in[0];
    const float* istate = (const float*)d_in[1];
    const float* emb    = (const float*)d_in[2];
    const float* encW   = (const float*)d_in[3];
    const float* Wih0   = (const float*)d_in[4];
    const float* Whh0   = (const float*)d_in[5];
    const float* bih0   = (const float*)d_in[6];
    const float* bhh0   = (const float*)d_in[7];
    const float* Wih1   = (const float*)d_in[8];
    const float* Whh1   = (const float*)d_in[9];
    const float* bih1   = (const float*)d_in[10];
    const float* bhh1   = (const float*)d_in[11];
    const float* PW     = (const float*)d_in[12];
    const float* PB     = (const float*)d_in[13];
    float* out = (float*)d_out;

    pack_kernel<<<(G4 * 2048) / 256, 256>>>(Wih0, Whh0, Wih1, Whh1, bih0, bhh0, bih1, bhh1);
    h0init_kernel<<<32, 128>>>(istate, encW);
    embx_kernel<<<dim3(TT, 32), 256>>>(ids, emb);
    for (int t = 0; t < TT; t++) {
        cell_kernel<<<128, 128>>>(t, 0);
        cell_kernel<<<128, 128>>>(t, 1);
    }
    proj_kernel<<<dim3(TT, 250), 256>>>(PW, PB, out);
    preds_kernel<<<16, 256>>>(out);
}